// round 6
// baseline (speedup 1.0000x reference)
#include <cuda_runtime.h>
#include <cuda_fp16.h>

#define BATCH 8
#define CDIM 64
#define HEADS 2
#define HW 65536
#define QKV_CH 192

#define NCHUNK 16
#define PART_STRIDE 1088   // 1024 Gram + 32 qnorm + 32 knorm

// Scratch (allocation forbidden -> device globals). fp16 intermediate.
__device__ __half g_qkv_h[(size_t)BATCH * QKV_CH * HW];   // after 1x1 conv (pre-dw)
__device__ float  g_part[BATCH * HEADS * NCHUNK * PART_STRIDE];
__device__ float  g_M[BATCH * CDIM * CDIM];

typedef unsigned long long u64;

__device__ __forceinline__ void fma2(u64 &d, u64 a, u64 b) {
    asm("fma.rn.f32x2 %0, %1, %2, %0;" : "+l"(d) : "l"(a), "l"(b));
}
__device__ __forceinline__ u64 dup2(float v) {
    unsigned int bb = __float_as_uint(v);
    return ((u64)bb << 32) | bb;
}
__device__ __forceinline__ u64 pack2(float lo, float hi) {
    return (u64)__float_as_uint(lo) | ((u64)__float_as_uint(hi) << 32);
}
__device__ __forceinline__ float lo2(u64 p) { return __uint_as_float((unsigned int)p); }
__device__ __forceinline__ float hi2(u64 p) { return __uint_as_float((unsigned int)(p >> 32)); }

__device__ __forceinline__ void unp8(uint4 raw, float* cv) {
    float2 f;
    f = __half22float2(*(__half2*)&raw.x); cv[0] = f.x; cv[1] = f.y;
    f = __half22float2(*(__half2*)&raw.y); cv[2] = f.x; cv[3] = f.y;
    f = __half22float2(*(__half2*)&raw.z); cv[4] = f.x; cv[5] = f.y;
    f = __half22float2(*(__half2*)&raw.w); cv[6] = f.x; cv[7] = f.y;
}

// Accumulate one 3-tap row of the depthwise conv for 8 consecutive pixels.
__device__ __forceinline__ void dw_row_acc(const __half* rowp, int x0,
                                           float w0, float w1, float w2, float* acc) {
    uint4 raw = *(const uint4*)(rowp + x0);
    float cv[8]; unp8(raw, cv);
    float l = (x0 > 0)   ? __half2float(rowp[x0 - 1]) : 0.f;
    float r = (x0 < 248) ? __half2float(rowp[x0 + 8]) : 0.f;
    acc[0] += w0 * l + w1 * cv[0] + w2 * cv[1];
#pragma unroll
    for (int j = 1; j < 7; ++j)
        acc[j] += w0 * cv[j - 1] + w1 * cv[j] + w2 * cv[j + 1];
    acc[7] += w0 * cv[6] + w1 * cv[7] + w2 * r;
}

// ---------------------------------------------------------------------------
// K1: qkv 1x1 conv. 256 threads, 256-px tile, thread tile 8px x 8out,
// 3 chunks of 64 output channels. fp32 math (f32x2), fp16 stores.
// ---------------------------------------------------------------------------
__global__ __launch_bounds__(256, 2) void k_qkv(const float* __restrict__ x,
                                                const float* __restrict__ w) {
    __shared__ float sx[64 * 256];     // [i][px]
    __shared__ u64 sw[64 * 64];        // [i][o] lane-duplicated
    const int gp = blockIdx.x * 256;
    const int b = gp >> 16, base = gp & 65535;
    const float* xb = x + (size_t)b * CDIM * HW + base;

    for (int t = threadIdx.x; t < 4096; t += 256) {
        int i = t >> 6, p4 = t & 63;
        ((float4*)sx)[t] = ((const float4*)(xb + (size_t)i * HW))[p4];
    }

    const int og = threadIdx.x >> 5, pg = threadIdx.x & 31;

    for (int c = 0; c < 3; ++c) {
        __syncthreads();
        for (int t = threadIdx.x; t < 4096; t += 256) {
            int o = t & 63, i = t >> 6;
            sw[t] = dup2(w[(c * 64 + o) * 64 + i]);
        }
        __syncthreads();

        u64 acc[8][4];
#pragma unroll
        for (int o = 0; o < 8; ++o)
#pragma unroll
            for (int s = 0; s < 4; ++s) acc[o][s] = 0ull;

#pragma unroll 4
        for (int i = 0; i < 64; ++i) {
            u64 xp[4];
#pragma unroll
            for (int s = 0; s < 4; ++s)
                xp[s] = *(const u64*)&sx[i * 256 + pg * 2 + s * 64];
#pragma unroll
            for (int o = 0; o < 8; ++o) {
                u64 wv = sw[i * 64 + og * 8 + o];
#pragma unroll
                for (int s = 0; s < 4; ++s) fma2(acc[o][s], wv, xp[s]);
            }
        }
#pragma unroll
        for (int o = 0; o < 8; ++o) {
            int ch = c * 64 + og * 8 + o;
            __half* dst = g_qkv_h + ((size_t)b * QKV_CH + ch) * HW + base;
#pragma unroll
            for (int s = 0; s < 4; ++s)
                *(__half2*)&dst[pg * 2 + s * 64] =
                    __floats2half2_rn(lo2(acc[o][s]), hi2(acc[o][s]));
        }
    }
}

// ---------------------------------------------------------------------------
// K2: fused depthwise(q,k) + Gram partials + norms.
// grid (16 rowgroups, 16 bh), block 256. Each block: 16 image rows.
// 3-row raw-qkv ring in smem; dw computed per row into packed f32 pairs.
// ---------------------------------------------------------------------------
__global__ __launch_bounds__(256) void k_gram_dw(const float* __restrict__ wdw) {
    const int bh = blockIdx.y;
    const int b = bh >> 1, hh = bh & 1;
    const int r0 = blockIdx.x * 16;

    __shared__ __align__(16) __half sraw[3][64][256];   // 96KB: ch 0..31=q, 32..63=k
    __shared__ u64 sq[32][129];                          // dw(q) packed pairs
    __shared__ u64 sk[32][129];                          // dw(k) packed pairs
    __shared__ float swt[64][9];

    for (int t = threadIdx.x; t < 576; t += 256) {
        int ch = t / 9, j = t % 9;
        int gch = (ch < 32) ? (hh * 32 + ch) : (64 + hh * 32 + (ch - 32));
        swt[ch][j] = wdw[gch * 9 + j];
    }

    auto load_row = [&](int row, int slot) {
        for (int idx = threadIdx.x; idx < 2048; idx += 256) {
            int ch = idx >> 5, p8 = idx & 31;
            uint4 val = make_uint4(0u, 0u, 0u, 0u);
            if (row >= 0 && row <= 255) {
                int gch = (ch < 32) ? (hh * 32 + ch) : (64 + hh * 32 + (ch - 32));
                val = *(const uint4*)&g_qkv_h[((size_t)b * QKV_CH + gch) * HW
                                              + row * 256 + p8 * 8];
            }
            *(uint4*)&sraw[slot][ch][p8 * 8] = val;
        }
    };

    const int ch_d = threadIdx.x >> 2, seg = threadIdx.x & 3;
    const int c0 = (threadIdx.x >> 4) * 2, d0 = (threadIdx.x & 15) * 2;
    const int nr = threadIdx.x >> 5, ncn = threadIdx.x & 31;

    u64 a00 = 0, a01 = 0, a10 = 0, a11 = 0, nacc = 0;

    load_row(r0 - 1, 0);
    load_row(r0, 1);

    for (int y = 0; y < 16; ++y) {
        load_row(r0 + y + 1, (y + 2) % 3);
        __syncthreads();
        // depthwise for image row r0+y -> sq / sk
        {
            const __half* rm = sraw[(y    ) % 3][ch_d];
            const __half* rc = sraw[(y + 1) % 3][ch_d];
            const __half* rp = sraw[(y + 2) % 3][ch_d];
            const float* W = swt[ch_d];
            u64* dst = (ch_d < 32) ? &sq[ch_d][0] : &sk[ch_d - 32][0];
#pragma unroll
            for (int c8 = 0; c8 < 8; ++c8) {
                int x0 = seg * 64 + c8 * 8;
                float acc[8] = {0.f, 0.f, 0.f, 0.f, 0.f, 0.f, 0.f, 0.f};
                dw_row_acc(rm, x0, W[0], W[1], W[2], acc);
                dw_row_acc(rc, x0, W[3], W[4], W[5], acc);
                dw_row_acc(rp, x0, W[6], W[7], W[8], acc);
                int pi = x0 >> 1;
                dst[pi + 0] = pack2(acc[0], acc[1]);
                dst[pi + 1] = pack2(acc[2], acc[3]);
                dst[pi + 2] = pack2(acc[4], acc[5]);
                dst[pi + 3] = pack2(acc[6], acc[7]);
            }
        }
        __syncthreads();
        // Gram accumulate over this row's 128 pairs (2x2 cells per thread)
#pragma unroll 4
        for (int pp = 0; pp < 128; ++pp) {
            u64 q0 = sq[c0][pp], q1 = sq[c0 + 1][pp];
            u64 k0 = sk[d0][pp], k1 = sk[d0 + 1][pp];
            fma2(a00, q0, k0); fma2(a01, q0, k1);
            fma2(a10, q1, k0); fma2(a11, q1, k1);
        }
        if (threadIdx.x < 64) {
#pragma unroll 4
            for (int pp = 0; pp < 128; ++pp) {
                u64 v = nr ? sk[ncn][pp] : sq[ncn][pp];
                fma2(nacc, v, v);
            }
        }
        // next load_row writes slot (y+3)%3==y%3 (read only by dw, already synced)
    }

    float* out = g_part + (size_t)(bh * NCHUNK + blockIdx.x) * PART_STRIDE;
    out[(c0    ) * 32 + d0    ] = lo2(a00) + hi2(a00);
    out[(c0    ) * 32 + d0 + 1] = lo2(a01) + hi2(a01);
    out[(c0 + 1) * 32 + d0    ] = lo2(a10) + hi2(a10);
    out[(c0 + 1) * 32 + d0 + 1] = lo2(a11) + hi2(a11);
    if (threadIdx.x < 64) out[1024 + threadIdx.x] = lo2(nacc) + hi2(nacc);
}

// ---------------------------------------------------------------------------
// K3: reduce -> attn -> 3x topk softmax -> combine -> fold proj into M
// grid: 16 (one per b,h)
// ---------------------------------------------------------------------------
__global__ __launch_bounds__(256) void k_attn(const float* __restrict__ wproj,
                                              const float* __restrict__ temp,
                                              const float* __restrict__ a1,
                                              const float* __restrict__ a2,
                                              const float* __restrict__ a3) {
    const int bh = blockIdx.x;
    const int b = bh >> 1, hh = bh & 1;
    __shared__ float sG[32][32];
    __shared__ float sN[2][32];
    __shared__ float sA[32][32];

    for (int cell = threadIdx.x; cell < 1024; cell += 256) {
        const float* p = g_part + (size_t)(bh * NCHUNK) * PART_STRIDE + cell;
        float s = 0.f;
#pragma unroll
        for (int ck = 0; ck < NCHUNK; ++ck) s += p[(size_t)ck * PART_STRIDE];
        sG[cell >> 5][cell & 31] = s;
    }
    if (threadIdx.x < 64) {
        int rr = threadIdx.x >> 5, c = threadIdx.x & 31;
        const float* p = g_part + (size_t)(bh * NCHUNK) * PART_STRIDE + 1024 + rr * 32 + c;
        float s = 0.f;
#pragma unroll
        for (int ck = 0; ck < NCHUNK; ++ck) s += p[(size_t)ck * PART_STRIDE];
        sN[rr][c] = s;
    }
    __syncthreads();

    if (threadIdx.x < 32) {
        const int c = threadIdx.x;
        float qn = fmaxf(sqrtf(sN[0][c]), 1e-12f);
        const float tmp = temp[hh];
        float row[32];
#pragma unroll
        for (int d = 0; d < 32; ++d) {
            float kn = fmaxf(sqrtf(sN[1][d]), 1e-12f);
            row[d] = sG[c][d] / (qn * kn) * tmp;
        }
        float tv[32];
#pragma unroll
        for (int d = 0; d < 32; ++d) tv[d] = row[d];
        float t16 = 0.f, t21 = 0.f, t24 = 0.f, m0 = 0.f;
        for (int rr = 0; rr < 24; ++rr) {
            float mx = -3.4e38f; int mi = 0;
#pragma unroll
            for (int d = 0; d < 32; ++d)
                if (tv[d] > mx) { mx = tv[d]; mi = d; }
            tv[mi] = -3.4e38f;
            if (rr == 0)  m0  = mx;
            if (rr == 15) t16 = mx;
            if (rr == 20) t21 = mx;
            if (rr == 23) t24 = mx;
        }
        float e[32];
        float s16 = 0.f, s21 = 0.f, s24 = 0.f;
#pragma unroll
        for (int d = 0; d < 32; ++d) {
            float ev = expf(row[d] - m0);
            e[d] = ev;
            if (row[d] >= t16) s16 += ev;
            if (row[d] >= t21) s21 += ev;
            if (row[d] >= t24) s24 += ev;
        }
        const float w1 = a1[0] / s16, w2 = a2[0] / s21, w3 = a3[0] / s24;
#pragma unroll
        for (int d = 0; d < 32; ++d) {
            float ww = 0.f;
            if (row[d] >= t16) ww += w1;
            if (row[d] >= t21) ww += w2;
            if (row[d] >= t24) ww += w3;
            sA[c][d] = e[d] * ww;
        }
    }
    __syncthreads();

    for (int t = threadIdx.x; t < 2048; t += 256) {
        int o = t >> 5, d = t & 31;
        float s = 0.f;
#pragma unroll
        for (int cc = 0; cc < 32; ++cc)
            s += wproj[o * 64 + hh * 32 + cc] * sA[cc][d];
        g_M[(b * 64 + o) * 64 + hh * 32 + d] = s;
    }
}

// ---------------------------------------------------------------------------
// K4: fused depthwise(v) + y = M @ dw(v). One block per image row (2048).
// ---------------------------------------------------------------------------
__global__ __launch_bounds__(256) void k_out_dw(const float* __restrict__ wdw,
                                                float* __restrict__ out) {
    const int gid = blockIdx.x;         // b*256 + y
    const int b = gid >> 8, y = gid & 255;
    __shared__ __align__(16) __half sraw[3][64][256];   // raw v rows y-1,y,y+1
    __shared__ u64 sv[64][129];                          // dw(v) packed pairs
    __shared__ u64 sM[64 * 64];                          // [ch][o] dup2
    __shared__ float swt[64][9];

    for (int t = threadIdx.x; t < 576; t += 256) {
        int ch = t / 9, j = t % 9;
        swt[ch][j] = wdw[(128 + ch) * 9 + j];
    }
    for (int idx = threadIdx.x; idx < 6144; idx += 256) {
        int s = idx >> 11, l = idx & 2047;
        int ch = l >> 5, p8 = l & 31;
        int row = y + s - 1;
        uint4 val = make_uint4(0u, 0u, 0u, 0u);
        if (row >= 0 && row <= 255)
            val = *(const uint4*)&g_qkv_h[((size_t)b * QKV_CH + 128 + ch) * HW
                                          + row * 256 + p8 * 8];
        *(uint4*)&sraw[s][ch][p8 * 8] = val;
    }
    for (int t = threadIdx.x; t < 4096; t += 256) {
        int o = t & 63, ch = t >> 6;
        sM[ch * 64 + o] = dup2(g_M[(b * 64 + o) * 64 + ch]);
    }
    __syncthreads();

    {   // depthwise v -> sv
        const int ch = threadIdx.x >> 2, seg = threadIdx.x & 3;
        const float* W = swt[ch];
#pragma unroll
        for (int c8 = 0; c8 < 8; ++c8) {
            int x0 = seg * 64 + c8 * 8;
            float acc[8] = {0.f, 0.f, 0.f, 0.f, 0.f, 0.f, 0.f, 0.f};
            dw_row_acc(sraw[0][ch], x0, W[0], W[1], W[2], acc);
            dw_row_acc(sraw[1][ch], x0, W[3], W[4], W[5], acc);
            dw_row_acc(sraw[2][ch], x0, W[6], W[7], W[8], acc);
            int pi = x0 >> 1;
            sv[ch][pi + 0] = pack2(acc[0], acc[1]);
            sv[ch][pi + 1] = pack2(acc[2], acc[3]);
            sv[ch][pi + 2] = pack2(acc[4], acc[5]);
            sv[ch][pi + 3] = pack2(acc[6], acc[7]);
        }
    }
    __syncthreads();

    const int og = threadIdx.x >> 5, pg = threadIdx.x & 31;
    u64 acc[8][4];
#pragma unroll
    for (int o = 0; o < 8; ++o)
#pragma unroll
        for (int s = 0; s < 4; ++s) acc[o][s] = 0ull;

#pragma unroll 4
    for (int ch = 0; ch < 64; ++ch) {
        u64 xp[4];
#pragma unroll
        for (int s = 0; s < 4; ++s)
            xp[s] = sv[ch][pg + s * 32];
#pragma unroll
        for (int o = 0; o < 8; ++o) {
            u64 wv = sM[ch * 64 + og * 8 + o];
#pragma unroll
            for (int s = 0; s < 4; ++s) fma2(acc[o][s], wv, xp[s]);
        }
    }
#pragma unroll
    for (int o = 0; o < 8; ++o) {
        int ochan = og * 8 + o;
        float* dst = out + ((size_t)b * CDIM + ochan) * HW + y * 256;
#pragma unroll
        for (int s = 0; s < 4; ++s)
            *(float2*)&dst[pg * 2 + s * 64] = make_float2(lo2(acc[o][s]), hi2(acc[o][s]));
    }
}

// ---------------------------------------------------------------------------
extern "C" void kernel_launch(void* const* d_in, const int* in_sizes, int n_in,
                              void* d_out, int out_size) {
    (void)in_sizes; (void)n_in; (void)out_size;
    const float* x     = (const float*)d_in[0];
    const float* wqkv  = (const float*)d_in[1];
    const float* wdw   = (const float*)d_in[2];
    const float* wproj = (const float*)d_in[3];
    const float* temp  = (const float*)d_in[4];
    const float* a1    = (const float*)d_in[5];
    const float* a2    = (const float*)d_in[6];
    const float* a3    = (const float*)d_in[7];

    k_qkv    <<<2048, 256>>>(x, wqkv);
    k_gram_dw<<<dim3(16, 16), 256>>>(wdw);
    k_attn   <<<16, 256>>>(wproj, temp, a1, a2, a3);
    k_out_dw <<<2048, 256>>>(wdw, (float*)d_out);
}

// round 9
// speedup vs baseline: 1.5827x; 1.5827x over previous
#include <cuda_runtime.h>
#include <cuda_fp16.h>
#include <mma.h>
using namespace nvcuda;

#define BATCH 8
#define CDIM 64
#define HEADS 2
#define HW 65536
#define QKV_CH 192

#define NCHUNK 16
#define PART_STRIDE 1088   // 1024 Gram + 32 qnorm + 32 knorm

// Scratch (allocation forbidden -> device globals). fp16 intermediates.
__device__ __half g_qkv_h[(size_t)BATCH * QKV_CH * HW];
__device__ __half g_dw_h [(size_t)BATCH * QKV_CH * HW];
__device__ float  g_part[BATCH * HEADS * NCHUNK * PART_STRIDE];
__device__ float  g_M[BATCH * CDIM * CDIM];

typedef unsigned long long u64;

__device__ __forceinline__ void fma2(u64 &d, u64 a, u64 b) {
    asm("fma.rn.f32x2 %0, %1, %2, %0;" : "+l"(d) : "l"(a), "l"(b));
}
__device__ __forceinline__ u64 pack2(float lo, float hi) {
    return (u64)__float_as_uint(lo) | ((u64)__float_as_uint(hi) << 32);
}
__device__ __forceinline__ float lo2(u64 p) { return __uint_as_float((unsigned int)p); }
__device__ __forceinline__ float hi2(u64 p) { return __uint_as_float((unsigned int)(p >> 32)); }

__device__ __forceinline__ void split_h(float v, __half &hi, __half &lo) {
    hi = __float2half_rn(v);
    lo = __float2half_rn(v - __half2float(hi));
}

// ---------------------------------------------------------------------------
// K1: qkv 1x1 conv via split-fp16 HMMA (fp32-class accuracy).
// Block: 512 threads (16 warps 4x4), 128-px tile, all 192 outputs.
// C = (Whi+Wlo)(Xhi+Xlo) ~= Whi*Xhi + Whi*Xlo + Wlo*Xhi  (fp32 accum).
// ---------------------------------------------------------------------------
__global__ __launch_bounds__(512) void k_qkv(const float* __restrict__ x,
                                             const float* __restrict__ w) {
    __shared__ __half swhi[192][72], swlo[192][72];
    __shared__ __half sxhi[64][136], sxlo[64][136];
    __shared__ float  scc[16][256];

    const int b    = blockIdx.x >> 9;
    const int base = (blockIdx.x & 511) * 128;
    const float* xb = x + (size_t)b * CDIM * HW + base;

    for (int t = threadIdx.x; t < 2048; t += 512) {
        int ch = t >> 5, p4 = t & 31;
        float4 v = *(const float4*)(xb + (size_t)ch * HW + p4 * 4);
        __half hi, lo;
        split_h(v.x, hi, lo); sxhi[ch][p4*4+0] = hi; sxlo[ch][p4*4+0] = lo;
        split_h(v.y, hi, lo); sxhi[ch][p4*4+1] = hi; sxlo[ch][p4*4+1] = lo;
        split_h(v.z, hi, lo); sxhi[ch][p4*4+2] = hi; sxlo[ch][p4*4+2] = lo;
        split_h(v.w, hi, lo); sxhi[ch][p4*4+3] = hi; sxlo[ch][p4*4+3] = lo;
    }
    for (int t = threadIdx.x; t < 3072; t += 512) {
        int o = t >> 4, seg = t & 15;
        float4 v = *(const float4*)(w + o * 64 + seg * 4);
        __half hi, lo;
        split_h(v.x, hi, lo); swhi[o][seg*4+0] = hi; swlo[o][seg*4+0] = lo;
        split_h(v.y, hi, lo); swhi[o][seg*4+1] = hi; swlo[o][seg*4+1] = lo;
        split_h(v.z, hi, lo); swhi[o][seg*4+2] = hi; swlo[o][seg*4+2] = lo;
        split_h(v.w, hi, lo); swhi[o][seg*4+3] = hi; swlo[o][seg*4+3] = lo;
    }
    __syncthreads();

    const int wid  = threadIdx.x >> 5;
    const int lane = threadIdx.x & 31;
    const int wm = wid >> 2, wn = wid & 3;
    const int m0 = wm * 48, n0 = wn * 32;

    wmma::fragment<wmma::accumulator, 16, 16, 16, float> acc[3][2];
#pragma unroll
    for (int i = 0; i < 3; ++i)
#pragma unroll
        for (int j = 0; j < 2; ++j) wmma::fill_fragment(acc[i][j], 0.f);

#pragma unroll
    for (int ks = 0; ks < 4; ++ks) {
        wmma::fragment<wmma::matrix_a, 16, 16, 16, __half, wmma::row_major> ah[3], al[3];
#pragma unroll
        for (int i = 0; i < 3; ++i) {
            wmma::load_matrix_sync(ah[i], &swhi[m0 + i * 16][ks * 16], 72);
            wmma::load_matrix_sync(al[i], &swlo[m0 + i * 16][ks * 16], 72);
        }
#pragma unroll
        for (int j = 0; j < 2; ++j) {
            wmma::fragment<wmma::matrix_b, 16, 16, 16, __half, wmma::row_major> bh, bl;
            wmma::load_matrix_sync(bh, &sxhi[ks * 16][n0 + j * 16], 136);
            wmma::load_matrix_sync(bl, &sxlo[ks * 16][n0 + j * 16], 136);
#pragma unroll
            for (int i = 0; i < 3; ++i) {
                wmma::mma_sync(acc[i][j], ah[i], bh, acc[i][j]);
                wmma::mma_sync(acc[i][j], ah[i], bl, acc[i][j]);
                wmma::mma_sync(acc[i][j], al[i], bh, acc[i][j]);
            }
        }
    }

    const int r = lane >> 1, c0 = (lane & 1) * 8;
#pragma unroll
    for (int i = 0; i < 3; ++i)
#pragma unroll
        for (int j = 0; j < 2; ++j) {
            wmma::store_matrix_sync(&scc[wid][0], acc[i][j], 16, wmma::mem_row_major);
            __syncwarp();
            int ch = m0 + i * 16 + r;
            __half* dst = g_qkv_h + ((size_t)b * QKV_CH + ch) * HW
                          + base + n0 + j * 16 + c0;
            const float* sp = &scc[wid][r * 16 + c0];
            uint4 pk;
            *(__half2*)&pk.x = __floats2half2_rn(sp[0], sp[1]);
            *(__half2*)&pk.y = __floats2half2_rn(sp[2], sp[3]);
            *(__half2*)&pk.z = __floats2half2_rn(sp[4], sp[5]);
            *(__half2*)&pk.w = __floats2half2_rn(sp[6], sp[7]);
            *(uint4*)dst = pk;
            __syncwarp();
        }
}

// ---------------------------------------------------------------------------
// K2: depthwise 3x3, fp16 in/out, 8 px per thread, fp32 math.
// ---------------------------------------------------------------------------
__global__ __launch_bounds__(256) void k_dw(const float* __restrict__ wdw) {
    const int gid = blockIdx.x * 256 + threadIdx.x;
    const int p8 = gid & 8191;
    const int bc = gid >> 13;
    const int ch = bc % QKV_CH;
    const int y = p8 >> 5, x0 = (p8 & 31) * 8;
    const __half* src = g_qkv_h + (size_t)bc * HW;
    const float* W = wdw + ch * 9;
    float acc[8];
#pragma unroll
    for (int j = 0; j < 8; ++j) acc[j] = 0.f;

#pragma unroll
    for (int dy = -1; dy <= 1; ++dy) {
        int yy = y + dy;
        if (yy < 0 || yy > 255) continue;
        const __half* row = src + yy * 256 + x0;
        uint4 raw = *(const uint4*)row;
        float cv[8];
        {
            float2 f;
            f = __half22float2(*(__half2*)&raw.x); cv[0] = f.x; cv[1] = f.y;
            f = __half22float2(*(__half2*)&raw.y); cv[2] = f.x; cv[3] = f.y;
            f = __half22float2(*(__half2*)&raw.z); cv[4] = f.x; cv[5] = f.y;
            f = __half22float2(*(__half2*)&raw.w); cv[6] = f.x; cv[7] = f.y;
        }
        float l = (x0 > 0)   ? __half2float(row[-1]) : 0.f;
        float r = (x0 < 248) ? __half2float(row[8])  : 0.f;
        float w0 = W[(dy + 1) * 3 + 0], w1 = W[(dy + 1) * 3 + 1], w2 = W[(dy + 1) * 3 + 2];
        acc[0] += w0 * l     + w1 * cv[0] + w2 * cv[1];
#pragma unroll
        for (int j = 1; j < 7; ++j)
            acc[j] += w0 * cv[j - 1] + w1 * cv[j] + w2 * cv[j + 1];
        acc[7] += w0 * cv[6] + w1 * cv[7] + w2 * r;
    }
    uint4 outp;
    *(__half2*)&outp.x = __floats2half2_rn(acc[0], acc[1]);
    *(__half2*)&outp.y = __floats2half2_rn(acc[2], acc[3]);
    *(__half2*)&outp.z = __floats2half2_rn(acc[4], acc[5]);
    *(__half2*)&outp.w = __floats2half2_rn(acc[6], acc[7]);
    *(uint4*)(g_dw_h + (size_t)bc * HW + y * 256 + x0) = outp;
}

// ---------------------------------------------------------------------------
// K3: Gram partials from fp16 q,k (fp32 math). grid (16, 16 bh), block 256.
// ---------------------------------------------------------------------------
__global__ __launch_bounds__(256) void k_gram() {
    const int bh = blockIdx.y, chunk = blockIdx.x;
    const int b = bh >> 1, hh = bh & 1;
    const __half* qb = g_dw_h + (size_t)b * QKV_CH * HW + (size_t)(hh * 32) * HW;
    const __half* kb = qb + (size_t)64 * HW;
    __shared__ u64 sq[32][33];
    __shared__ u64 sk[32][33];
    const int base = chunk * 4096;
    const int c0 = (threadIdx.x >> 4) * 2, d0 = (threadIdx.x & 15) * 2;
    const int r = threadIdx.x >> 5, cn = threadIdx.x & 31;

    u64 a00 = 0, a01 = 0, a10 = 0, a11 = 0, nacc = 0;

    for (int tile = 0; tile < 64; ++tile) {
        const int tb = base + tile * 64;
        for (int t = threadIdx.x; t < 1024; t += 256) {
            int half_ = t >> 9, l = t & 511;
            int cc = l >> 4, pp2 = (l & 15) * 2;
            const __half* src = half_ ? kb : qb;
            uint2 raw = *(const uint2*)&src[(size_t)cc * HW + tb + 2 * pp2];
            float2 f0 = __half22float2(*(__half2*)&raw.x);
            float2 f1 = __half22float2(*(__half2*)&raw.y);
            u64* dst = half_ ? &sk[cc][pp2] : &sq[cc][pp2];
            dst[0] = pack2(f0.x, f0.y);
            dst[1] = pack2(f1.x, f1.y);
        }
        __syncthreads();
#pragma unroll
        for (int pp = 0; pp < 32; ++pp) {
            u64 q0 = sq[c0][pp], q1 = sq[c0 + 1][pp];
            u64 k0 = sk[d0][pp], k1 = sk[d0 + 1][pp];
            fma2(a00, q0, k0); fma2(a01, q0, k1);
            fma2(a10, q1, k0); fma2(a11, q1, k1);
        }
        if (threadIdx.x < 64) {
#pragma unroll
            for (int pp = 0; pp < 32; ++pp) {
                u64 v = r ? sk[cn][pp] : sq[cn][pp];
                fma2(nacc, v, v);
            }
        }
        __syncthreads();
    }
    float* out = g_part + (size_t)(bh * NCHUNK + chunk) * PART_STRIDE;
    out[(c0    ) * 32 + d0    ] = lo2(a00) + hi2(a00);
    out[(c0    ) * 32 + d0 + 1] = lo2(a01) + hi2(a01);
    out[(c0 + 1) * 32 + d0    ] = lo2(a10) + hi2(a10);
    out[(c0 + 1) * 32 + d0 + 1] = lo2(a11) + hi2(a11);
    if (threadIdx.x < 64) out[1024 + threadIdx.x] = lo2(nacc) + hi2(nacc);
}

// ---------------------------------------------------------------------------
// K4: reduce -> attn -> 3x topk softmax -> combine -> fold proj into M
// ---------------------------------------------------------------------------
__global__ __launch_bounds__(256) void k_attn(const float* __restrict__ wproj,
                                              const float* __restrict__ temp,
                                              const float* __restrict__ a1,
                                              const float* __restrict__ a2,
                                              const float* __restrict__ a3) {
    const int bh = blockIdx.x;
    const int b = bh >> 1, hh = bh & 1;
    __shared__ float sG[32][32];
    __shared__ float sN[2][32];
    __shared__ float sA[32][32];

    for (int cell = threadIdx.x; cell < 1024; cell += 256) {
        const float* p = g_part + (size_t)(bh * NCHUNK) * PART_STRIDE + cell;
        float s = 0.f;
#pragma unroll
        for (int ck = 0; ck < NCHUNK; ++ck) s += p[(size_t)ck * PART_STRIDE];
        sG[cell >> 5][cell & 31] = s;
    }
    if (threadIdx.x < 64) {
        int rr = threadIdx.x >> 5, c = threadIdx.x & 31;
        const float* p = g_part + (size_t)(bh * NCHUNK) * PART_STRIDE + 1024 + rr * 32 + c;
        float s = 0.f;
#pragma unroll
        for (int ck = 0; ck < NCHUNK; ++ck) s += p[(size_t)ck * PART_STRIDE];
        sN[rr][c] = s;
    }
    __syncthreads();

    if (threadIdx.x < 32) {
        const int c = threadIdx.x;
        float qn = fmaxf(sqrtf(sN[0][c]), 1e-12f);
        const float tmp = temp[hh];
        float row[32];
#pragma unroll
        for (int d = 0; d < 32; ++d) {
            float kn = fmaxf(sqrtf(sN[1][d]), 1e-12f);
            row[d] = sG[c][d] / (qn * kn) * tmp;
        }
        float tv[32];
#pragma unroll
        for (int d = 0; d < 32; ++d) tv[d] = row[d];
        float t16 = 0.f, t21 = 0.f, t24 = 0.f, m0 = 0.f;
        for (int rr = 0; rr < 24; ++rr) {
            float mx = -3.4e38f; int mi = 0;
#pragma unroll
            for (int d = 0; d < 32; ++d)
                if (tv[d] > mx) { mx = tv[d]; mi = d; }
            tv[mi] = -3.4e38f;
            if (rr == 0)  m0  = mx;
            if (rr == 15) t16 = mx;
            if (rr == 20) t21 = mx;
            if (rr == 23) t24 = mx;
        }
        float e[32];
        float s16 = 0.f, s21 = 0.f, s24 = 0.f;
#pragma unroll
        for (int d = 0; d < 32; ++d) {
            float ev = expf(row[d] - m0);
            e[d] = ev;
            if (row[d] >= t16) s16 += ev;
            if (row[d] >= t21) s21 += ev;
            if (row[d] >= t24) s24 += ev;
        }
        const float w1 = a1[0] / s16, w2 = a2[0] / s21, w3 = a3[0] / s24;
#pragma unroll
        for (int d = 0; d < 32; ++d) {
            float ww = 0.f;
            if (row[d] >= t16) ww += w1;
            if (row[d] >= t21) ww += w2;
            if (row[d] >= t24) ww += w3;
            sA[c][d] = e[d] * ww;
        }
    }
    __syncthreads();

    for (int t = threadIdx.x; t < 2048; t += 256) {
        int o = t >> 5, d = t & 31;
        float s = 0.f;
#pragma unroll
        for (int cc = 0; cc < 32; ++cc)
            s += wproj[o * 64 + hh * 32 + cc] * sA[cc][d];
        g_M[(b * 64 + o) * 64 + hh * 32 + d] = s;
    }
}

// ---------------------------------------------------------------------------
// K5: y = M @ v via split-M HMMA. Block: 512 threads, 256-px tile.
// M split hi/lo (fp32-class); v single fp16 (as stored); fp32 accum -> gmem.
// ---------------------------------------------------------------------------
__global__ __launch_bounds__(512) void k_out(float* __restrict__ out) {
    __shared__ __half sMhi[64][72], sMlo[64][72];
    __shared__ __half sV[64][264];
    const int gp = blockIdx.x * 256;
    const int b = gp >> 16, base = gp & 65535;
    const __half* vb = g_dw_h + ((size_t)b * QKV_CH + 128) * HW + base;

    for (int t = threadIdx.x; t < 4096; t += 512) {
        int m = t >> 6, k = t & 63;
        __half hi, lo;
        split_h(g_M[b * 4096 + t], hi, lo);
        sMhi[m][k] = hi; sMlo[m][k] = lo;
    }
    for (int t = threadIdx.x; t < 2048; t += 512) {
        int ch = t >> 5, p8 = t & 31;
        *(uint4*)&sV[ch][p8 * 8] = *(const uint4*)&vb[(size_t)ch * HW + p8 * 8];
    }
    __syncthreads();

    const int wid = threadIdx.x >> 5;
    const int wm = wid >> 2, wn = wid & 3;
    const int m0 = wm * 16, n0 = wn * 64;

    wmma::fragment<wmma::accumulator, 16, 16, 16, float> acc[4];
#pragma unroll
    for (int j = 0; j < 4; ++j) wmma::fill_fragment(acc[j], 0.f);

#pragma unroll
    for (int ks = 0; ks < 4; ++ks) {
        wmma::fragment<wmma::matrix_a, 16, 16, 16, __half, wmma::row_major> ah, al;
        wmma::load_matrix_sync(ah, &sMhi[m0][ks * 16], 72);
        wmma::load_matrix_sync(al, &sMlo[m0][ks * 16], 72);
#pragma unroll
        for (int j = 0; j < 4; ++j) {
            wmma::fragment<wmma::matrix_b, 16, 16, 16, __half, wmma::row_major> bf;
            wmma::load_matrix_sync(bf, &sV[ks * 16][n0 + j * 16], 264);
            wmma::mma_sync(acc[j], ah, bf, acc[j]);
            wmma::mma_sync(acc[j], al, bf, acc[j]);
        }
    }
#pragma unroll
    for (int j = 0; j < 4; ++j)
        wmma::store_matrix_sync(out + ((size_t)b * CDIM + m0) * HW + base + n0 + j * 16,
                                acc[j], HW, wmma::mem_row_major);
}

// ---------------------------------------------------------------------------
extern "C" void kernel_launch(void* const* d_in, const int* in_sizes, int n_in,
                              void* d_out, int out_size) {
    (void)in_sizes; (void)n_in; (void)out_size;
    const float* x     = (const float*)d_in[0];
    const float* wqkv  = (const float*)d_in[1];
    const float* wdw   = (const float*)d_in[2];
    const float* wproj = (const float*)d_in[3];
    const float* temp  = (const float*)d_in[4];
    const float* a1    = (const float*)d_in[5];
    const float* a2    = (const float*)d_in[6];
    const float* a3    = (const float*)d_in[7];

    k_qkv <<<4096, 512>>>(x, wqkv);
    k_dw  <<<49152, 256>>>(wdw);
    k_gram<<<dim3(NCHUNK, BATCH * HEADS), 256>>>();
    k_attn<<<16, 256>>>(wproj, temp, a1, a2, a3);
    k_out <<<2048, 512>>>((float*)d_out);
}

// round 13
// speedup vs baseline: 2.3864x; 1.5078x over previous
#include <cuda_runtime.h>
#include <cuda_fp16.h>
#include <mma.h>
using namespace nvcuda;

#define BATCH 8
#define CDIM 64
#define HEADS 2
#define HW 65536
#define QKV_CH 192

#define NCHUNK 16
#define PART_STRIDE 1088   // 1024 Gram + 32 qnorm + 32 knorm

// Scratch (allocation forbidden -> device globals). fp16 intermediates.
__device__ __half g_qkv_h[(size_t)BATCH * QKV_CH * HW];
__device__ __half g_dw_h [(size_t)BATCH * QKV_CH * HW];
__device__ float  g_part[BATCH * HEADS * NCHUNK * PART_STRIDE];
__device__ float  g_M[BATCH * CDIM * CDIM];

typedef unsigned long long u64;

__device__ __forceinline__ void fma2(u64 &d, u64 a, u64 b) {
    asm("fma.rn.f32x2 %0, %1, %2, %0;" : "+l"(d) : "l"(a), "l"(b));
}
__device__ __forceinline__ u64 pack2(float lo, float hi) {
    return (u64)__float_as_uint(lo) | ((u64)__float_as_uint(hi) << 32);
}
__device__ __forceinline__ float lo2(u64 p) { return __uint_as_float((unsigned int)p); }
__device__ __forceinline__ float hi2(u64 p) { return __uint_as_float((unsigned int)(p >> 32)); }

__device__ __forceinline__ void split_h(float v, __half &hi, __half &lo) {
    hi = __float2half_rn(v);
    lo = __float2half_rn(v - __half2float(hi));
}

// ---------------------------------------------------------------------------
// K1: qkv 1x1 conv via split-fp16 HMMA (fp32-class accuracy).
// ---------------------------------------------------------------------------
__global__ __launch_bounds__(512) void k_qkv(const float* __restrict__ x,
                                             const float* __restrict__ w) {
    __shared__ __half swhi[192][72], swlo[192][72];
    __shared__ __half sxhi[64][136], sxlo[64][136];
    __shared__ float  scc[16][256];

    const int b    = blockIdx.x >> 9;
    const int base = (blockIdx.x & 511) * 128;
    const float* xb = x + (size_t)b * CDIM * HW + base;

    for (int t = threadIdx.x; t < 2048; t += 512) {
        int ch = t >> 5, p4 = t & 31;
        float4 v = *(const float4*)(xb + (size_t)ch * HW + p4 * 4);
        __half hi, lo;
        split_h(v.x, hi, lo); sxhi[ch][p4*4+0] = hi; sxlo[ch][p4*4+0] = lo;
        split_h(v.y, hi, lo); sxhi[ch][p4*4+1] = hi; sxlo[ch][p4*4+1] = lo;
        split_h(v.z, hi, lo); sxhi[ch][p4*4+2] = hi; sxlo[ch][p4*4+2] = lo;
        split_h(v.w, hi, lo); sxhi[ch][p4*4+3] = hi; sxlo[ch][p4*4+3] = lo;
    }
    for (int t = threadIdx.x; t < 3072; t += 512) {
        int o = t >> 4, seg = t & 15;
        float4 v = *(const float4*)(w + o * 64 + seg * 4);
        __half hi, lo;
        split_h(v.x, hi, lo); swhi[o][seg*4+0] = hi; swlo[o][seg*4+0] = lo;
        split_h(v.y, hi, lo); swhi[o][seg*4+1] = hi; swlo[o][seg*4+1] = lo;
        split_h(v.z, hi, lo); swhi[o][seg*4+2] = hi; swlo[o][seg*4+2] = lo;
        split_h(v.w, hi, lo); swhi[o][seg*4+3] = hi; swlo[o][seg*4+3] = lo;
    }
    __syncthreads();

    const int wid  = threadIdx.x >> 5;
    const int lane = threadIdx.x & 31;
    const int wm = wid >> 2, wn = wid & 3;
    const int m0 = wm * 48, n0 = wn * 32;

    wmma::fragment<wmma::accumulator, 16, 16, 16, float> acc[3][2];
#pragma unroll
    for (int i = 0; i < 3; ++i)
#pragma unroll
        for (int j = 0; j < 2; ++j) wmma::fill_fragment(acc[i][j], 0.f);

#pragma unroll
    for (int ks = 0; ks < 4; ++ks) {
        wmma::fragment<wmma::matrix_a, 16, 16, 16, __half, wmma::row_major> ah[3], al[3];
#pragma unroll
        for (int i = 0; i < 3; ++i) {
            wmma::load_matrix_sync(ah[i], &swhi[m0 + i * 16][ks * 16], 72);
            wmma::load_matrix_sync(al[i], &swlo[m0 + i * 16][ks * 16], 72);
        }
#pragma unroll
        for (int j = 0; j < 2; ++j) {
            wmma::fragment<wmma::matrix_b, 16, 16, 16, __half, wmma::row_major> bh, bl;
            wmma::load_matrix_sync(bh, &sxhi[ks * 16][n0 + j * 16], 136);
            wmma::load_matrix_sync(bl, &sxlo[ks * 16][n0 + j * 16], 136);
#pragma unroll
            for (int i = 0; i < 3; ++i) {
                wmma::mma_sync(acc[i][j], ah[i], bh, acc[i][j]);
                wmma::mma_sync(acc[i][j], ah[i], bl, acc[i][j]);
                wmma::mma_sync(acc[i][j], al[i], bh, acc[i][j]);
            }
        }
    }

    const int r = lane >> 1, c0 = (lane & 1) * 8;
#pragma unroll
    for (int i = 0; i < 3; ++i)
#pragma unroll
        for (int j = 0; j < 2; ++j) {
            wmma::store_matrix_sync(&scc[wid][0], acc[i][j], 16, wmma::mem_row_major);
            __syncwarp();
            int ch = m0 + i * 16 + r;
            __half* dst = g_qkv_h + ((size_t)b * QKV_CH + ch) * HW
                          + base + n0 + j * 16 + c0;
            const float* sp = &scc[wid][r * 16 + c0];
            uint4 pk;
            *(__half2*)&pk.x = __floats2half2_rn(sp[0], sp[1]);
            *(__half2*)&pk.y = __floats2half2_rn(sp[2], sp[3]);
            *(__half2*)&pk.z = __floats2half2_rn(sp[4], sp[5]);
            *(__half2*)&pk.w = __floats2half2_rn(sp[6], sp[7]);
            *(uint4*)dst = pk;
            __syncwarp();
        }
}

// ---------------------------------------------------------------------------
// K2: depthwise 3x3, fp16 in/out, 8 px per thread, fp32 math.
// ---------------------------------------------------------------------------
__global__ __launch_bounds__(256) void k_dw(const float* __restrict__ wdw) {
    const int gid = blockIdx.x * 256 + threadIdx.x;
    const int p8 = gid & 8191;
    const int bc = gid >> 13;
    const int ch = bc % QKV_CH;
    const int y = p8 >> 5, x0 = (p8 & 31) * 8;
    const __half* src = g_qkv_h + (size_t)bc * HW;
    const float* W = wdw + ch * 9;
    float acc[8];
#pragma unroll
    for (int j = 0; j < 8; ++j) acc[j] = 0.f;

#pragma unroll
    for (int dy = -1; dy <= 1; ++dy) {
        int yy = y + dy;
        if (yy < 0 || yy > 255) continue;
        const __half* row = src + yy * 256 + x0;
        uint4 raw = *(const uint4*)row;
        float cv[8];
        {
            float2 f;
            f = __half22float2(*(__half2*)&raw.x); cv[0] = f.x; cv[1] = f.y;
            f = __half22float2(*(__half2*)&raw.y); cv[2] = f.x; cv[3] = f.y;
            f = __half22float2(*(__half2*)&raw.z); cv[4] = f.x; cv[5] = f.y;
            f = __half22float2(*(__half2*)&raw.w); cv[6] = f.x; cv[7] = f.y;
        }
        float l = (x0 > 0)   ? __half2float(row[-1]) : 0.f;
        float r = (x0 < 248) ? __half2float(row[8])  : 0.f;
        float w0 = W[(dy + 1) * 3 + 0], w1 = W[(dy + 1) * 3 + 1], w2 = W[(dy + 1) * 3 + 2];
        acc[0] += w0 * l     + w1 * cv[0] + w2 * cv[1];
#pragma unroll
        for (int j = 1; j < 7; ++j)
            acc[j] += w0 * cv[j - 1] + w1 * cv[j] + w2 * cv[j + 1];
        acc[7] += w0 * cv[6] + w1 * cv[7] + w2 * r;
    }
    uint4 outp;
    *(__half2*)&outp.x = __floats2half2_rn(acc[0], acc[1]);
    *(__half2*)&outp.y = __floats2half2_rn(acc[2], acc[3]);
    *(__half2*)&outp.z = __floats2half2_rn(acc[4], acc[5]);
    *(__half2*)&outp.w = __floats2half2_rn(acc[6], acc[7]);
    *(uint4*)(g_dw_h + (size_t)bc * HW + y * 256 + x0) = outp;
}

// ---------------------------------------------------------------------------
// K3: Gram partials via HMMA. grid (16 chunks, 16 bh), block 256 (8 warps).
// Each warp owns 2 k-steps per 256-px subtile; fp32 accum frags persist;
// block-reduce 8 partial 32x32 grams at the end. Norms via packed f32x2.
// ---------------------------------------------------------------------------
__global__ __launch_bounds__(256) void k_gram() {
    const int bh = blockIdx.y, chunk = blockIdx.x;
    const int b = bh >> 1, hh = bh & 1;
    const __half* qb = g_dw_h + (size_t)b * QKV_CH * HW + (size_t)(hh * 32) * HW;
    const __half* kb = qb + (size_t)64 * HW;

    __shared__ __half sQ[32][264];
    __shared__ __half sK[32][264];
    __shared__ float red[8][32][36];    // ldm 36 floats = 144B (16B multiple)
    __shared__ float nbuf[4][64];

    const int tid = threadIdx.x;
    const int wid = tid >> 5;
    const int nch = tid & 63, nseg = tid >> 6;     // norm: channel, 64-px segment

    wmma::fragment<wmma::accumulator, 16, 16, 16, float> acc[2][2];
#pragma unroll
    for (int i = 0; i < 2; ++i)
#pragma unroll
        for (int j = 0; j < 2; ++j) wmma::fill_fragment(acc[i][j], 0.f);

    u64 nacc = 0;
    const int base = chunk * 4096;

    for (int st = 0; st < 16; ++st) {
        const int tb = base + st * 256;
        for (int t = tid; t < 2048; t += 256) {
            int half_ = t >> 10, l = t & 1023;
            int cc = l >> 5, p8 = l & 31;
            const __half* src = half_ ? kb : qb;
            uint4 raw = *(const uint4*)&src[(size_t)cc * HW + tb + p8 * 8];
            __half* dst = half_ ? &sK[cc][p8 * 8] : &sQ[cc][p8 * 8];
            *(uint4*)dst = raw;
        }
        __syncthreads();

#pragma unroll
        for (int s = 0; s < 2; ++s) {
            const int k0 = (wid * 2 + s) * 16;
            wmma::fragment<wmma::matrix_a, 16, 16, 16, __half, wmma::row_major> a0, a1;
            wmma::fragment<wmma::matrix_b, 16, 16, 16, __half, wmma::col_major> b0, b1;
            wmma::load_matrix_sync(a0, &sQ[0][k0], 264);
            wmma::load_matrix_sync(a1, &sQ[16][k0], 264);
            wmma::load_matrix_sync(b0, &sK[0][k0], 264);
            wmma::load_matrix_sync(b1, &sK[16][k0], 264);
            wmma::mma_sync(acc[0][0], a0, b0, acc[0][0]);
            wmma::mma_sync(acc[0][1], a0, b1, acc[0][1]);
            wmma::mma_sync(acc[1][0], a1, b0, acc[1][0]);
            wmma::mma_sync(acc[1][1], a1, b1, acc[1][1]);
        }
        {   // norms: thread covers 64 px of one channel
            const __half2* srow = (const __half2*)((nch < 32) ? &sQ[nch][0]
                                                              : &sK[nch - 32][0])
                                  + nseg * 32;
#pragma unroll
            for (int i = 0; i < 32; ++i) {
                float2 f = __half22float2(srow[i]);
                u64 p = pack2(f.x, f.y);
                fma2(nacc, p, p);
            }
        }
        __syncthreads();
    }

    // block reduce: 8 partial grams + 4-seg norms
#pragma unroll
    for (int i = 0; i < 2; ++i)
#pragma unroll
        for (int j = 0; j < 2; ++j)
            wmma::store_matrix_sync(&red[wid][i * 16][j * 16], acc[i][j], 36,
                                    wmma::mem_row_major);
    nbuf[nseg][nch] = lo2(nacc) + hi2(nacc);
    __syncthreads();

    float* out = g_part + (size_t)(bh * NCHUNK + chunk) * PART_STRIDE;
    for (int t = tid; t < 1024; t += 256) {
        int c = t >> 5, d = t & 31;
        float s = 0.f;
#pragma unroll
        for (int w8 = 0; w8 < 8; ++w8) s += red[w8][c][d];
        out[t] = s;
    }
    if (tid < 64)
        out[1024 + tid] = nbuf[0][tid] + nbuf[1][tid] + nbuf[2][tid] + nbuf[3][tid];
}

// ---------------------------------------------------------------------------
// K4: reduce -> attn -> 3x topk softmax -> combine -> fold proj into M
// ---------------------------------------------------------------------------
__global__ __launch_bounds__(256) void k_attn(const float* __restrict__ wproj,
                                              const float* __restrict__ temp,
                                              const float* __restrict__ a1,
                                              const float* __restrict__ a2,
                                              const float* __restrict__ a3) {
    const int bh = blockIdx.x;
    const int b = bh >> 1, hh = bh & 1;
    __shared__ float sG[32][32];
    __shared__ float sN[2][32];
    __shared__ float sA[32][32];

    for (int cell = threadIdx.x; cell < 1024; cell += 256) {
        const float* p = g_part + (size_t)(bh * NCHUNK) * PART_STRIDE + cell;
        float s = 0.f;
#pragma unroll
        for (int ck = 0; ck < NCHUNK; ++ck) s += p[(size_t)ck * PART_STRIDE];
        sG[cell >> 5][cell & 31] = s;
    }
    if (threadIdx.x < 64) {
        int rr = threadIdx.x >> 5, c = threadIdx.x & 31;
        const float* p = g_part + (size_t)(bh * NCHUNK) * PART_STRIDE + 1024 + rr * 32 + c;
        float s = 0.f;
#pragma unroll
        for (int ck = 0; ck < NCHUNK; ++ck) s += p[(size_t)ck * PART_STRIDE];
        sN[rr][c] = s;
    }
    __syncthreads();

    if (threadIdx.x < 32) {
        const int c = threadIdx.x;
        float qn = fmaxf(sqrtf(sN[0][c]), 1e-12f);
        const float tmp = temp[hh];
        float row[32];
#pragma unroll
        for (int d = 0; d < 32; ++d) {
            float kn = fmaxf(sqrtf(sN[1][d]), 1e-12f);
            row[d] = sG[c][d] / (qn * kn) * tmp;
        }
        float tv[32];
#pragma unroll
        for (int d = 0; d < 32; ++d) tv[d] = row[d];
        float t16 = 0.f, t21 = 0.f, t24 = 0.f, m0 = 0.f;
        for (int rr = 0; rr < 24; ++rr) {
            float mx = -3.4e38f; int mi = 0;
#pragma unroll
            for (int d = 0; d < 32; ++d)
                if (tv[d] > mx) { mx = tv[d]; mi = d; }
            tv[mi] = -3.4e38f;
            if (rr == 0)  m0  = mx;
            if (rr == 15) t16 = mx;
            if (rr == 20) t21 = mx;
            if (rr == 23) t24 = mx;
        }
        float e[32];
        float s16 = 0.f, s21 = 0.f, s24 = 0.f;
#pragma unroll
        for (int d = 0; d < 32; ++d) {
            float ev = expf(row[d] - m0);
            e[d] = ev;
            if (row[d] >= t16) s16 += ev;
            if (row[d] >= t21) s21 += ev;
            if (row[d] >= t24) s24 += ev;
        }
        const float w1 = a1[0] / s16, w2 = a2[0] / s21, w3 = a3[0] / s24;
#pragma unroll
        for (int d = 0; d < 32; ++d) {
            float ww = 0.f;
            if (row[d] >= t16) ww += w1;
            if (row[d] >= t21) ww += w2;
            if (row[d] >= t24) ww += w3;
            sA[c][d] = e[d] * ww;
        }
    }
    __syncthreads();

    for (int t = threadIdx.x; t < 2048; t += 256) {
        int o = t >> 5, d = t & 31;
        float s = 0.f;
#pragma unroll
        for (int cc = 0; cc < 32; ++cc)
            s += wproj[o * 64 + hh * 32 + cc] * sA[cc][d];
        g_M[(b * 64 + o) * 64 + hh * 32 + d] = s;
    }
}

// ---------------------------------------------------------------------------
// K5: y = M @ v via split-M HMMA. Block: 512 threads, 256-px tile.
// ---------------------------------------------------------------------------
__global__ __launch_bounds__(512) void k_out(float* __restrict__ out) {
    __shared__ __half sMhi[64][72], sMlo[64][72];
    __shared__ __half sV[64][264];
    const int gp = blockIdx.x * 256;
    const int b = gp >> 16, base = gp & 65535;
    const __half* vb = g_dw_h + ((size_t)b * QKV_CH + 128) * HW + base;

    for (int t = threadIdx.x; t < 4096; t += 512) {
        int m = t >> 6, k = t & 63;
        __half hi, lo;
        split_h(g_M[b * 4096 + t], hi, lo);
        sMhi[m][k] = hi; sMlo[m][k] = lo;
    }
    for (int t = threadIdx.x; t < 2048; t += 512) {
        int ch = t >> 5, p8 = t & 31;
        *(uint4*)&sV[ch][p8 * 8] = *(const uint4*)&vb[(size_t)ch * HW + p8 * 8];
    }
    __syncthreads();

    const int wid = threadIdx.x >> 5;
    const int wm = wid >> 2, wn = wid & 3;
    const int m0 = wm * 16, n0 = wn * 64;

    wmma::fragment<wmma::accumulator, 16, 16, 16, float> acc[4];
#pragma unroll
    for (int j = 0; j < 4; ++j) wmma::fill_fragment(acc[j], 0.f);

#pragma unroll
    for (int ks = 0; ks < 4; ++ks) {
        wmma::fragment<wmma::matrix_a, 16, 16, 16, __half, wmma::row_major> ah, al;
        wmma::load_matrix_sync(ah, &sMhi[m0][ks * 16], 72);
        wmma::load_matrix_sync(al, &sMlo[m0][ks * 16], 72);
#pragma unroll
        for (int j = 0; j < 4; ++j) {
            wmma::fragment<wmma::matrix_b, 16, 16, 16, __half, wmma::row_major> bf;
            wmma::load_matrix_sync(bf, &sV[ks * 16][n0 + j * 16], 264);
            wmma::mma_sync(acc[j], ah, bf, acc[j]);
            wmma::mma_sync(acc[j], al, bf, acc[j]);
        }
    }
#pragma unroll
    for (int j = 0; j < 4; ++j)
        wmma::store_matrix_sync(out + ((size_t)b * CDIM + m0) * HW + base + n0 + j * 16,
                                acc[j], HW, wmma::mem_row_major);
}

// ---------------------------------------------------------------------------
extern "C" void kernel_launch(void* const* d_in, const int* in_sizes, int n_in,
                              void* d_out, int out_size) {
    (void)in_sizes; (void)n_in; (void)out_size;
    const float* x     = (const float*)d_in[0];
    const float* wqkv  = (const float*)d_in[1];
    const float* wdw   = (const float*)d_in[2];
    const float* wproj = (const float*)d_in[3];
    const float* temp  = (const float*)d_in[4];
    const float* a1    = (const float*)d_in[5];
    const float* a2    = (const float*)d_in[6];
    const float* a3    = (const float*)d_in[7];

    k_qkv <<<4096, 512>>>(x, wqkv);
    k_dw  <<<49152, 256>>>(wdw);
    k_gram<<<dim3(NCHUNK, BATCH * HEADS), 256>>>();
    k_attn<<<16, 256>>>(wproj, temp, a1, a2, a3);
    k_out <<<2048, 512>>>((float*)d_out);
}